// round 5
// baseline (speedup 1.0000x reference)
#include <cuda_runtime.h>
#include <math.h>

#define T_STEPS 1440
#define SEG_LEN 16
#define NSEG    90           // 1440 / 16
#define B_MAX   16384
#define WPB     4            // warps per block
#define NTILES  (B_MAX / 32) // 512

// Decoupled-lookback state. Separate partial/inclusive payload arrays so a
// flag upgrade (1 -> 2) can never produce a torn payload read.
__device__ float2 g_part[NSEG * B_MAX];
__device__ float2 g_incl[NSEG * B_MAX];
__device__ int    g_flag[NSEG * B_MAX];

struct Coefs { float k1, k2, k3, e1, e2, e3; };

__device__ __forceinline__ float bsig(float raw, float lo, float hi) {
    return lo + (hi - lo) / (1.0f + expf(-raw));
}

__device__ __forceinline__ Coefs get_coefs(
    const float* rRi, const float* rRe, const float* rCi, const float* rCe,
    const float* rAi, const float* rAe, const float* rHg)
{
    float Ri = bsig(rRi[0], 1e-4f, 0.2f);
    float Re = bsig(rRe[0], 1e-4f, 0.2f);
    float Ci = bsig(rCi[0], 1e5f,  1e8f);
    float Ce = bsig(rCe[0], 1e5f,  1e8f);
    float Ai = bsig(rAi[0], 0.0f,  0.2f);
    float Ae = bsig(rAe[0], 0.0f,  0.2f);
    float Hg = bsig(rHg[0], 1.0f,  2e4f);
    float dci = 300.0f / Ci;
    float dce = 300.0f / Ce;
    Coefs c;
    c.k1 = dci / Ri;  c.k2 = dci * Ai;  c.k3 = -dci * Hg;  // MODE_COOL
    c.e1 = dce / Ri;  c.e2 = dce / Re;  c.e3 = dce * Ae;
    return c;
}

// Warp-per-(32-building tile, 16-step segment). Local zero-init scan with
// outputs in registers; decoupled lookback; in-register correction; single
// coalesced write. 4 warps per block for occupancy.
__global__ void __launch_bounds__(32 * WPB) rc_lookback(
    const float4* __restrict__ in, float* __restrict__ out,
    const float* __restrict__ rRi, const float* __restrict__ rRe,
    const float* __restrict__ rCi, const float* __restrict__ rCe,
    const float* __restrict__ rAi, const float* __restrict__ rAe,
    const float* __restrict__ rHg, int B)
{
    // per-warp buffer: input chunk tile (32 rows x 9 float4, padded), later
    // reused as the output transpose stage (32 x 17 floats)
    __shared__ __align__(16) char sbuf[WPB][32 * 9 * 16];

    int w    = threadIdx.x >> 5;
    int lane = threadIdx.x & 31;
    float4* tile = reinterpret_cast<float4*>(sbuf[w]);

    int unit = blockIdx.x * WPB + w;
    int s    = unit >> 9;            // / NTILES(512); monotone in blockIdx
    int tl   = unit & 511;
    int b0   = tl * 32;
    int b    = b0 + lane;

    Coefs c = get_coefs(rRi, rRe, rCi, rCe, rAi, rAe, rHg);
    float a00 = 1.0f - c.k1, a01 = c.k1;
    float a10 = c.e1,        a11 = 1.0f - c.e1 - c.e2;

    const float4* base = in + (size_t)b0 * T_STEPS + s * SEG_LEN;
    int jr = lane & 7;     // t-col within 8-step chunk (load phase)
    int rr = lane >> 3;    // row-group (load phase)

    float outs[SEG_LEN];
    float pin = 0.0f, penv = 0.0f;
    bool first = (s == 0);

    #pragma unroll
    for (int ch = 0; ch < 2; ch++) {
        #pragma unroll
        for (int i = 0; i < 8; i++) {          // coalesced: 1 line per row
            int r = i * 4 + rr;
            tile[r * 9 + jr] = base[(size_t)r * T_STEPS + ch * 8 + jr];
        }
        __syncwarp();
        if (ch == 0 && first) {                // true initial condition
            float4 f0 = tile[lane * 9 + 0];
            pin  = f0.x;
            penv = 0.5f * (f0.x + f0.y);
        }
        #pragma unroll
        for (int j = 0; j < 8; j++) {
            float4 f = tile[lane * 9 + j];
            float t_out = f.y, hv = f.z, sol = f.w;
            float p    = fmaf(c.k2, sol, c.k3 * hv);
            float nin  = fmaf(c.k1, penv - pin, pin + p);
            float q    = fmaf(c.e3, sol, penv);
            float nenv = fmaf(c.e1, pin - penv, fmaf(c.e2, t_out - penv, q));
            pin = nin; penv = nenv;
            outs[ch * 8 + j] = nin;
        }
        __syncwarp();
    }

    int idx = s * B + b;
    float xi = 0.0f, xe = 0.0f;
    if (first) {
        g_incl[idx] = make_float2(pin, penv);
        __threadfence();
        *(volatile int*)&g_flag[idx] = 2;
    } else {
        g_part[idx] = make_float2(pin, penv);
        __threadfence();
        *(volatile int*)&g_flag[idx] = 1;

        // M = A^16 via 4 squarings
        float m00 = a00, m01 = a01, m10 = a10, m11 = a11;
        #pragma unroll
        for (int i = 0; i < 4; i++) {
            float tr  = m00 + m11;
            float n00 = fmaf(m00, m00, m01 * m10);
            float n11 = fmaf(m11, m11, m01 * m10);
            float n01 = m01 * tr;
            float n10 = m10 * tr;
            m00 = n00; m01 = n01; m10 = n10; m11 = n11;
        }

        // lookback: x_start = d_{s-1} + M d_{s-2} + ... + M^{s-1-i} incl_i
        float p00 = 1.0f, p01 = 0.0f, p10 = 0.0f, p11 = 1.0f;
        for (int i = s - 1; i >= 0; --i) {
            int pidx = i * B + b;
            int f;
            while ((f = *(volatile int*)&g_flag[pidx]) == 0) { __nanosleep(20); }
            __threadfence();
            const float* vp = (f == 2) ? (const float*)&g_incl[pidx]
                                       : (const float*)&g_part[pidx];
            float vx = *(volatile const float*)(vp + 0);
            float vy = *(volatile const float*)(vp + 1);
            xi = fmaf(p00, vx, fmaf(p01, vy, xi));
            xe = fmaf(p10, vx, fmaf(p11, vy, xe));
            if (f == 2) break;
            float q00 = fmaf(p00, m00, p01 * m10), q01 = fmaf(p00, m01, p01 * m11);
            float q10 = fmaf(p10, m00, p11 * m10), q11 = fmaf(p10, m01, p11 * m11);
            p00 = q00; p01 = q01; p10 = q10; p11 = q11;
        }

        // publish inclusive ASAP to unblock successors
        float ix = fmaf(m00, xi, fmaf(m01, xe, pin));
        float ie = fmaf(m10, xi, fmaf(m11, xe, penv));
        g_incl[idx] = make_float2(ix, ie);
        __threadfence();
        *(volatile int*)&g_flag[idx] = 2;

        // in-register correction: outs[j] += row0(A^{j+1}) . x_start
        float al = a00, be = a01;
        #pragma unroll
        for (int j = 0; j < SEG_LEN; j++) {
            outs[j] = fmaf(al, xi, fmaf(be, xe, outs[j]));
            float nal = fmaf(al, a00, be * a10);
            float nbe = fmaf(al, a01, be * a11);
            al = nal; be = nbe;
        }
    }

    // transpose through smem (reuse tile buffer): rows of 16 floats, padded 17
    __syncwarp();
    float* ot = reinterpret_cast<float*>(sbuf[w]);
    #pragma unroll
    for (int j = 0; j < SEG_LEN; j++) ot[lane * 17 + j] = outs[j];
    __syncwarp();
    // flush: 2 building-rows per instruction (16 floats each), all lanes active
    float* obase = out + (size_t)b0 * T_STEPS + s * SEG_LEN;
    int tr2 = lane & 15;          // t within segment
    int rh  = lane >> 4;          // which of the 2 rows
    #pragma unroll
    for (int i = 0; i < 16; i++) {
        int r = i * 2 + rh;
        obase[(size_t)r * T_STEPS + tr2] = ot[r * 17 + tr2];
    }
}

// ---------------------------------------------------------------------------
extern "C" void kernel_launch(void* const* d_in, const int* in_sizes, int n_in,
                              void* d_out, int out_size) {
    const float4* in  = (const float4*)d_in[0];
    const float* rRi = (const float*)d_in[1];
    const float* rRe = (const float*)d_in[2];
    const float* rCi = (const float*)d_in[3];
    const float* rCe = (const float*)d_in[4];
    const float* rAi = (const float*)d_in[5];
    const float* rAe = (const float*)d_in[6];
    const float* rHg = (const float*)d_in[7];
    float* out = (float*)d_out;

    int B = in_sizes[0] / (T_STEPS * 4);   // 16384

    // reset lookback flags (graph-capturable memset node; no allocation)
    void* flag_ptr = nullptr;
    cudaGetSymbolAddress(&flag_ptr, g_flag);
    cudaMemsetAsync(flag_ptr, 0, (size_t)NSEG * B_MAX * sizeof(int), 0);

    int units  = (B / 32) * NSEG;          // 46080
    int blocks = units / WPB;              // 11520
    rc_lookback<<<blocks, 32 * WPB>>>(in, out, rRi, rRe, rCi, rCe, rAi, rAe, rHg, B);
}

// round 7
// speedup vs baseline: 1.3779x; 1.3779x over previous
#include <cuda_runtime.h>
#include <cuda_pipeline.h>
#include <math.h>

#define T_STEPS 1440
#define SEG_LEN 32
#define NSEG    45           // 1440 / 32
#define B_MAX   16384

// Decoupled-lookback state. Separate partial/inclusive payload arrays so a
// flag upgrade (1 -> 2) can never produce a torn payload read.
__device__ float2 g_part[NSEG * B_MAX];
__device__ float2 g_incl[NSEG * B_MAX];
__device__ int    g_flag[NSEG * B_MAX];

struct Coefs { float k1, k2, k3, e1, e2, e3; };

__device__ __forceinline__ float bsig(float raw, float lo, float hi) {
    return lo + (hi - lo) / (1.0f + expf(-raw));
}

__device__ __forceinline__ Coefs get_coefs(
    const float* rRi, const float* rRe, const float* rCi, const float* rCe,
    const float* rAi, const float* rAe, const float* rHg)
{
    float Ri = bsig(rRi[0], 1e-4f, 0.2f);
    float Re = bsig(rRe[0], 1e-4f, 0.2f);
    float Ci = bsig(rCi[0], 1e5f,  1e8f);
    float Ce = bsig(rCe[0], 1e5f,  1e8f);
    float Ai = bsig(rAi[0], 0.0f,  0.2f);
    float Ae = bsig(rAe[0], 0.0f,  0.2f);
    float Hg = bsig(rHg[0], 1.0f,  2e4f);
    float dci = 300.0f / Ci;
    float dce = 300.0f / Ce;
    Coefs c;
    c.k1 = dci / Ri;  c.k2 = dci * Ai;  c.k3 = -dci * Hg;  // MODE_COOL
    c.e1 = dce / Ri;  c.e2 = dce / Re;  c.e3 = dce * Ae;
    return c;
}

// One warp-block per (32-building tile, 32-step segment). cp.async 2-stage
// chunk pipeline; XOR-swizzled smem tile; in-register outputs + lookback
// correction; coalesced flush through smem transpose.
__global__ void __launch_bounds__(32) rc_lookback(
    const float4* __restrict__ in, float* __restrict__ out,
    const float* __restrict__ rRi, const float* __restrict__ rRe,
    const float* __restrict__ rCi, const float* __restrict__ rCe,
    const float* __restrict__ rAi, const float* __restrict__ rAe,
    const float* __restrict__ rHg, int B)
{
    // two 4KB chunk buffers (32 rows x 8 float4, XOR swizzled);
    // first buffer reused as the 32x33-float output transpose stage afterwards.
    __shared__ __align__(16) char sbuf[2][32 * 8 * 16];

    int lane = threadIdx.x;
    int s    = blockIdx.y;
    int b0   = blockIdx.x * 32;
    int b    = b0 + lane;

    Coefs c = get_coefs(rRi, rRe, rCi, rCe, rAi, rAe, rHg);
    float a00 = 1.0f - c.k1, a01 = c.k1;
    float a10 = c.e1,        a11 = 1.0f - c.e1 - c.e2;

    const char* gbase = (const char*)(in + (size_t)b0 * T_STEPS + s * SEG_LEN);
    int jr = lane & 7;     // t-col within 8-step chunk (load phase)
    int rr = lane >> 3;    // row-group (load phase): 8 lanes per row

    // issue chunk ch's 8 coalesced 16B async copies for this lane
    auto issue_chunk = [&](int ch) {
        char* buf = sbuf[ch & 1];
        #pragma unroll
        for (int i = 0; i < 8; i++) {
            int r = i * 4 + rr;
            const char* src = gbase + ((size_t)r * T_STEPS + ch * 8 + jr) * 16;
            char* dst = buf + r * 128 + ((jr ^ (r & 7)) * 16);
            __pipeline_memcpy_async(dst, src, 16);
        }
        __pipeline_commit();
    };

    issue_chunk(0);
    issue_chunk(1);

    float outs[SEG_LEN];
    float pin = 0.0f, penv = 0.0f;
    bool first = (s == 0);

    #pragma unroll
    for (int ch = 0; ch < 4; ch++) {
        __pipeline_wait_prior(1);            // chunk ch resident
        __syncwarp();
        const float4* buf = reinterpret_cast<const float4*>(sbuf[ch & 1]);
        if (ch == 0 && first) {              // true initial condition
            float4 f0 = buf[lane * 8 + (0 ^ (lane & 7))];
            pin  = f0.x;
            penv = 0.5f * (f0.x + f0.y);
        }
        #pragma unroll
        for (int j = 0; j < 8; j++) {
            float4 f = buf[lane * 8 + (j ^ (lane & 7))];   // conflict-free
            float t_out = f.y, hv = f.z, sol = f.w;
            float p    = fmaf(c.k2, sol, c.k3 * hv);
            float nin  = fmaf(c.k1, penv - pin, pin + p);
            float q    = fmaf(c.e3, sol, penv);
            float nenv = fmaf(c.e1, pin - penv, fmaf(c.e2, t_out - penv, q));
            pin = nin; penv = nenv;
            outs[ch * 8 + j] = nin;
        }
        __syncwarp();
        if (ch + 2 < 4) issue_chunk(ch + 2);  // refill the buffer just freed
        else            __pipeline_commit();  // empty group: uniform count, no deadlock
    }

    int idx = s * B + b;
    float xi = 0.0f, xe = 0.0f;
    if (first) {
        g_incl[idx] = make_float2(pin, penv);
        __threadfence();
        *(volatile int*)&g_flag[idx] = 2;
    } else {
        g_part[idx] = make_float2(pin, penv);
        __threadfence();
        *(volatile int*)&g_flag[idx] = 1;

        // M = A^32 via 5 squarings
        float m00 = a00, m01 = a01, m10 = a10, m11 = a11;
        #pragma unroll
        for (int i = 0; i < 5; i++) {
            float tr  = m00 + m11;
            float n00 = fmaf(m00, m00, m01 * m10);
            float n11 = fmaf(m11, m11, m01 * m10);
            float n01 = m01 * tr;
            float n10 = m10 * tr;
            m00 = n00; m01 = n01; m10 = n10; m11 = n11;
        }

        // lookback: x_start = d_{s-1} + M d_{s-2} + ... + M^{s-1-i} incl_i
        float p00 = 1.0f, p01 = 0.0f, p10 = 0.0f, p11 = 1.0f;
        for (int i = s - 1; i >= 0; --i) {
            int pidx = i * B + b;
            int f;
            while ((f = *(volatile int*)&g_flag[pidx]) == 0) { __nanosleep(40); }
            __threadfence();
            const float* vp = (f == 2) ? (const float*)&g_incl[pidx]
                                       : (const float*)&g_part[pidx];
            float vx = *(volatile const float*)(vp + 0);
            float vy = *(volatile const float*)(vp + 1);
            xi = fmaf(p00, vx, fmaf(p01, vy, xi));
            xe = fmaf(p10, vx, fmaf(p11, vy, xe));
            if (f == 2) break;
            float q00 = fmaf(p00, m00, p01 * m10), q01 = fmaf(p00, m01, p01 * m11);
            float q10 = fmaf(p10, m00, p11 * m10), q11 = fmaf(p10, m01, p11 * m11);
            p00 = q00; p01 = q01; p10 = q10; p11 = q11;
        }

        // publish inclusive ASAP to unblock successors
        float ix = fmaf(m00, xi, fmaf(m01, xe, pin));
        float ie = fmaf(m10, xi, fmaf(m11, xe, penv));
        g_incl[idx] = make_float2(ix, ie);
        __threadfence();
        *(volatile int*)&g_flag[idx] = 2;

        // in-register correction: outs[j] += row0(A^{j+1}) . x_start
        float al = a00, be = a01;
        #pragma unroll
        for (int j = 0; j < SEG_LEN; j++) {
            outs[j] = fmaf(al, xi, fmaf(be, xe, outs[j]));
            float nal = fmaf(al, a00, be * a10);
            float nbe = fmaf(al, a01, be * a11);
            al = nal; be = nbe;
        }
    }

    // transpose through smem (reuse first chunk buffer: 4224B <= 4096+ spill
    // into second buffer via flat addressing), coalesced 128B row stores
    __syncwarp();
    float* ot = reinterpret_cast<float*>(&sbuf[0][0]);
    #pragma unroll
    for (int j = 0; j < SEG_LEN; j++) ot[lane * 33 + j] = outs[j];  // stride 33: conflict-free
    __syncwarp();
    float* obase = out + (size_t)b0 * T_STEPS + s * SEG_LEN;
    #pragma unroll
    for (int r = 0; r < 32; r++)
        __stcs(obase + (size_t)r * T_STEPS + lane, ot[r * 33 + lane]);
}

// ---------------------------------------------------------------------------
extern "C" void kernel_launch(void* const* d_in, const int* in_sizes, int n_in,
                              void* d_out, int out_size) {
    const float4* in  = (const float4*)d_in[0];
    const float* rRi = (const float*)d_in[1];
    const float* rRe = (const float*)d_in[2];
    const float* rCi = (const float*)d_in[3];
    const float* rCe = (const float*)d_in[4];
    const float* rAi = (const float*)d_in[5];
    const float* rAe = (const float*)d_in[6];
    const float* rHg = (const float*)d_in[7];
    float* out = (float*)d_out;

    int B = in_sizes[0] / (T_STEPS * 4);   // 16384

    // reset lookback flags (graph-capturable memset node; no allocation)
    void* flag_ptr = nullptr;
    cudaGetSymbolAddress(&flag_ptr, g_flag);
    cudaMemsetAsync(flag_ptr, 0, (size_t)NSEG * B_MAX * sizeof(int), 0);

    dim3 grid(B / 32, NSEG);
    rc_lookback<<<grid, 32>>>(in, out, rRi, rRe, rCi, rCe, rAi, rAe, rHg, B);
}